// round 1
// baseline (speedup 1.0000x reference)
#include <cuda_runtime.h>

#define N_NODES 100000
#define H 128
#define HH 64

// ---- scratch (device globals: no allocation allowed) ----
__device__ float g_neigh[(size_t)N_NODES * H];    // 51.2 MB
__device__ float g_invfeat[(size_t)N_NODES * H];  // 51.2 MB
__device__ float g_deg[N_NODES];

// Transposed weight block layout (float offsets):
//   W1T [128][64] @ 0      (k*64 + j)
//   B1  [64]      @ 8192
//   W2T [64][64]  @ 8256   (k*64 + j)
//   B2  [64]      @ 12352
//   W3T [64][128] @ 12416  (k*128 + j)
//   B3  [128]     @ 20608
#define WBLK 20736

__device__ __forceinline__ void load_weights(float* Wt,
    const float* w1, const float* b1, const float* w2, const float* b2,
    const float* w3, const float* b3)
{
    int t = threadIdx.x, T = blockDim.x;
    for (int i = t; i < HH * H; i += T) { int j = i >> 7, k = i & 127; Wt[k * HH + j] = w1[i]; }
    for (int i = t; i < HH; i += T) Wt[8192 + i] = b1[i];
    for (int i = t; i < HH * HH; i += T) { int j = i >> 6, k = i & 63; Wt[8256 + k * HH + j] = w2[i]; }
    for (int i = t; i < HH; i += T) Wt[12352 + i] = b2[i];
    for (int i = t; i < H * HH; i += T) { int j = i >> 6, k = i & 63; Wt[12416 + k * H + j] = w3[i]; }
    for (int i = t; i < H; i += T) Wt[20608 + i] = b3[i];
}

__device__ __forceinline__ float getc(float4 v, int c) {
    return c == 0 ? v.x : c == 1 ? v.y : c == 2 ? v.z : v.w;
}
__device__ __forceinline__ float lrelu(float x) { return x >= 0.f ? x : 0.01f * x; }

// Warp computes the 3-layer MLP for 4 rows at once.
// buf: per-warp smem, X rows at [e*128], H1 at 512 + e*64, H2 at 768 + e*64.
// Lane owns output columns 4*lane..4*lane+3 of each row (returned in out[e]).
__device__ __forceinline__ void mlp3_warp4(const float* __restrict__ Wt,
                                           float* __restrict__ buf,
                                           float4 out[4], int lane)
{
    const float2* W1 = (const float2*)Wt;
    const float2* B1 = (const float2*)(Wt + 8192);
    const float2* W2 = (const float2*)(Wt + 8256);
    const float2* B2 = (const float2*)(Wt + 12352);
    const float4* W3 = (const float4*)(Wt + 12416);
    const float4* B3 = (const float4*)(Wt + 20608);
    float* Xb = buf;
    float* H1 = buf + 4 * H;   // 512
    float* H2 = H1 + 4 * HH;   // 768

    // ---- layer 1: 128 -> 64, lrelu ----
    {
        float2 b = B1[lane];
        float2 a[4] = { b, b, b, b };
        #pragma unroll
        for (int kk = 0; kk < 32; kk++) {
            float4 x[4];
            #pragma unroll
            for (int e = 0; e < 4; e++) x[e] = ((const float4*)(Xb + e * H))[kk];
            #pragma unroll
            for (int c = 0; c < 4; c++) {
                float2 w = W1[(kk * 4 + c) * 32 + lane];
                #pragma unroll
                for (int e = 0; e < 4; e++) {
                    float s = getc(x[e], c);
                    a[e].x = fmaf(w.x, s, a[e].x);
                    a[e].y = fmaf(w.y, s, a[e].y);
                }
            }
        }
        #pragma unroll
        for (int e = 0; e < 4; e++) {
            float2 v; v.x = lrelu(a[e].x); v.y = lrelu(a[e].y);
            ((float2*)(H1 + e * HH))[lane] = v;
        }
    }
    __syncwarp();

    // ---- layer 2: 64 -> 64, lrelu ----
    {
        float2 b = B2[lane];
        float2 a[4] = { b, b, b, b };
        #pragma unroll
        for (int kk = 0; kk < 16; kk++) {
            float4 x[4];
            #pragma unroll
            for (int e = 0; e < 4; e++) x[e] = ((const float4*)(H1 + e * HH))[kk];
            #pragma unroll
            for (int c = 0; c < 4; c++) {
                float2 w = W2[(kk * 4 + c) * 32 + lane];
                #pragma unroll
                for (int e = 0; e < 4; e++) {
                    float s = getc(x[e], c);
                    a[e].x = fmaf(w.x, s, a[e].x);
                    a[e].y = fmaf(w.y, s, a[e].y);
                }
            }
        }
        #pragma unroll
        for (int e = 0; e < 4; e++) {
            float2 v; v.x = lrelu(a[e].x); v.y = lrelu(a[e].y);
            ((float2*)(H2 + e * HH))[lane] = v;
        }
    }
    __syncwarp();

    // ---- layer 3: 64 -> 128 (linear) ----
    {
        float4 b = B3[lane];
        float4 a[4] = { b, b, b, b };
        #pragma unroll
        for (int kk = 0; kk < 16; kk++) {
            float4 x[4];
            #pragma unroll
            for (int e = 0; e < 4; e++) x[e] = ((const float4*)(H2 + e * HH))[kk];
            #pragma unroll
            for (int c = 0; c < 4; c++) {
                float4 w = W3[(kk * 4 + c) * 32 + lane];
                #pragma unroll
                for (int e = 0; e < 4; e++) {
                    float s = getc(x[e], c);
                    a[e].x = fmaf(w.x, s, a[e].x);
                    a[e].y = fmaf(w.y, s, a[e].y);
                    a[e].z = fmaf(w.z, s, a[e].z);
                    a[e].w = fmaf(w.w, s, a[e].w);
                }
            }
        }
        #pragma unroll
        for (int e = 0; e < 4; e++) out[e] = a[e];
    }
}

// ---------------------------------------------------------------------------
__global__ void zero_kernel()
{
    int idx = blockIdx.x * blockDim.x + threadIdx.x;
    const int total4 = N_NODES * H / 4;
    if (idx < total4) ((float4*)g_neigh)[idx] = make_float4(0.f, 0.f, 0.f, 0.f);
    if (idx < N_NODES) g_deg[idx] = 0.f;
}

// ---------------------------------------------------------------------------
#define PW 16  // warps per block (precompute)
__global__ void precompute_inv_kernel(const float* __restrict__ feat,
    const float* __restrict__ w1, const float* __restrict__ b1,
    const float* __restrict__ w2, const float* __restrict__ b2,
    const float* __restrict__ w3, const float* __restrict__ b3)
{
    extern __shared__ __align__(16) float smem[];
    float* Wt = smem;
    load_weights(Wt, w1, b1, w2, b2, w3, b3);
    __syncthreads();

    int lane = threadIdx.x & 31;
    int warp = threadIdx.x >> 5;
    float* buf = smem + WBLK + warp * 1024;
    int row0 = (blockIdx.x * PW + warp) * 4;
    if (row0 >= N_NODES) return;

    #pragma unroll
    for (int e = 0; e < 4; e++) {
        int rr = min(row0 + e, N_NODES - 1);
        ((float4*)(buf + e * H))[lane] = ((const float4*)(feat + (size_t)rr * H))[lane];
    }
    __syncwarp();

    float4 out[4];
    mlp3_warp4(Wt, buf, out, lane);

    #pragma unroll
    for (int e = 0; e < 4; e++) {
        int rr = row0 + e;
        if (rr < N_NODES) ((float4*)(g_invfeat + (size_t)rr * H))[lane] = out[e];
    }
}

// ---------------------------------------------------------------------------
__global__ void edge_kernel(const float* __restrict__ feat,
    const int* __restrict__ src, const int* __restrict__ dst,
    const int* __restrict__ r, int E)
{
    int gw = (blockIdx.x * blockDim.x + threadIdx.x) >> 5;
    int lane = threadIdx.x & 31;
    if (gw >= E) return;
    int s = 0, d = 0, rr = 0;
    if (lane == 0) { s = src[gw]; d = dst[gw]; rr = r[gw]; }
    s = __shfl_sync(0xFFFFFFFFu, s, 0);
    d = __shfl_sync(0xFFFFFFFFu, d, 0);
    rr = __shfl_sync(0xFFFFFFFFu, rr, 0);

    const float* base = rr ? g_invfeat : feat;
    float4 v = ((const float4*)(base + (size_t)s * H))[lane];
    float* p = g_neigh + (size_t)d * H + lane * 4;
    asm volatile("red.global.add.v4.f32 [%0], {%1,%2,%3,%4};"
                 :: "l"(p), "f"(v.x), "f"(v.y), "f"(v.z), "f"(v.w) : "memory");
    if (lane == 0) atomicAdd(&g_deg[d], 1.0f);
}

// ---------------------------------------------------------------------------
#define NW 12  // warps per block (node apply; 2 weight sets in smem)
__global__ void node_kernel(const int* __restrict__ inv, float* __restrict__ out,
    const float* aw1, const float* ab1, const float* aw2, const float* ab2,
    const float* aw3, const float* ab3,
    const float* iw1, const float* ib1, const float* iw2, const float* ib2,
    const float* iw3, const float* ib3)
{
    extern __shared__ __align__(16) float smem[];
    float* WtA = smem;
    float* WtI = smem + WBLK;
    load_weights(WtA, aw1, ab1, aw2, ab2, aw3, ab3);
    load_weights(WtI, iw1, ib1, iw2, ib2, iw3, ib3);
    __syncthreads();

    int lane = threadIdx.x & 31;
    int warp = threadIdx.x >> 5;
    float* buf = smem + 2 * WBLK + warp * 1024;
    int row0 = (blockIdx.x * NW + warp) * 4;
    if (row0 >= N_NODES) return;

    int flags = 0;
    #pragma unroll
    for (int e = 0; e < 4; e++) {
        int rr = min(row0 + e, N_NODES - 1);
        float inv_dg = 1.0f / fmaxf(g_deg[rr], 1.0f);
        float4 v = ((const float4*)(g_neigh + (size_t)rr * H))[lane];
        v.x *= inv_dg; v.y *= inv_dg; v.z *= inv_dg; v.w *= inv_dg;
        ((float4*)(buf + e * H))[lane] = v;
        if (row0 + e < N_NODES && inv[row0 + e]) flags |= (1 << e);  // warp-uniform
    }
    __syncwarp();

    float4 res[4];
    mlp3_warp4(WtA, buf, res, lane);

    float4 fin[4];
    #pragma unroll
    for (int e = 0; e < 4; e++) fin[e] = res[e];

    if (flags) {
        __syncwarp();
        #pragma unroll
        for (int e = 0; e < 4; e++) ((float4*)(buf + e * H))[lane] = res[e];
        __syncwarp();
        float4 res2[4];
        mlp3_warp4(WtI, buf, res2, lane);
        #pragma unroll
        for (int e = 0; e < 4; e++) if ((flags >> e) & 1) fin[e] = res2[e];
    }

    #pragma unroll
    for (int e = 0; e < 4; e++) {
        int rr = row0 + e;
        if (rr < N_NODES) ((float4*)(out + (size_t)rr * H))[lane] = fin[e];
    }
}

// ---------------------------------------------------------------------------
extern "C" void kernel_launch(void* const* d_in, const int* in_sizes, int n_in,
                              void* d_out, int out_size)
{
    const float* feat = (const float*)d_in[0];
    const int* src = (const int*)d_in[1];
    const int* dst = (const int*)d_in[2];
    const int* r   = (const int*)d_in[3];
    const int* inv = (const int*)d_in[4];
    const float* iw1 = (const float*)d_in[5],  *ib1 = (const float*)d_in[6];
    const float* iw2 = (const float*)d_in[7],  *ib2 = (const float*)d_in[8];
    const float* iw3 = (const float*)d_in[9],  *ib3 = (const float*)d_in[10];
    const float* aw1 = (const float*)d_in[11], *ab1 = (const float*)d_in[12];
    const float* aw2 = (const float*)d_in[13], *ab2 = (const float*)d_in[14];
    const float* aw3 = (const float*)d_in[15], *ab3 = (const float*)d_in[16];
    int E = in_sizes[1];
    float* out = (float*)d_out;

    // 1) zero scratch
    {
        int total4 = N_NODES * H / 4;
        zero_kernel<<<(total4 + 255) / 256, 256>>>();
    }
    // 2) inv_feat = mlp_inv(feat) for all nodes (amortizes edge-side MLP 4x)
    {
        size_t sm = (size_t)(WBLK + PW * 1024) * sizeof(float);
        cudaFuncSetAttribute(precompute_inv_kernel,
                             cudaFuncAttributeMaxDynamicSharedMemorySize, (int)sm);
        int blocks = (N_NODES + PW * 4 - 1) / (PW * 4);
        precompute_inv_kernel<<<blocks, PW * 32, sm>>>(feat, iw1, ib1, iw2, ib2, iw3, ib3);
    }
    // 3) edge gather + scatter-add (warp per edge, v4 float reductions)
    {
        int blocks = (E + 7) / 8;
        edge_kernel<<<blocks, 256>>>(feat, src, dst, r, E);
    }
    // 4) node apply: mean, and-MLP, conditional inv-MLP
    {
        size_t sm = (size_t)(2 * WBLK + NW * 1024) * sizeof(float);
        cudaFuncSetAttribute(node_kernel,
                             cudaFuncAttributeMaxDynamicSharedMemorySize, (int)sm);
        int blocks = (N_NODES + NW * 4 - 1) / (NW * 4);
        node_kernel<<<blocks, NW * 32, sm>>>(inv, out,
            aw1, ab1, aw2, ab2, aw3, ab3,
            iw1, ib1, iw2, ib2, iw3, ib3);
    }
}

// round 10
// speedup vs baseline: 1.0735x; 1.0735x over previous
#include <cuda_runtime.h>
#include <cstdint>

#define N_NODES 100000
#define H 128
#define HH 64
#define TPB 256
#define WARPS 8
#define RPW 8                               // rows per warp
#define ROWS_PER_CTA (WARPS * RPW)          // 64
#define NT ((N_NODES + ROWS_PER_CTA - 1) / ROWS_PER_CTA)

// ---- scratch (device globals: no allocation allowed) ----
__device__ float g_neigh[(size_t)N_NODES * H];    // 51.2 MB
__device__ float g_invfeat[(size_t)N_NODES * H];  // 51.2 MB (later holds res)
__device__ float g_deg[N_NODES];

// smem (floats): Wt region [8192 weights + 128 bias] | per-warp bufs 2048 each
#define WT_F   8320
#define BUF_F  (WARPS * 2048)
#define SMEM_F (WT_F + BUF_F)
#define SMEM_BYTES (SMEM_F * 4)             // 98816 B -> 2 CTAs/SM

__device__ __forceinline__ float lrelu(float x) { return x >= 0.f ? x : 0.01f * x; }
__device__ __forceinline__ float getc(float4 v, int c) {
    return c == 0 ? v.x : c == 1 ? v.y : c == 2 ? v.z : v.w;
}

// stage W [N][2^lgK] row-major -> transposed WtT[k*N + n]; bias -> Wt+8192
__device__ __forceinline__ void stage_w(float* Wt, const float* w, const float* b,
                                        int N, int lgK)
{
    int K = 1 << lgK;
    int tot = N << lgK;
    for (int i = threadIdx.x; i < tot; i += TPB) {
        int n = i >> lgK, k = i & (K - 1);
        Wt[k * N + n] = w[i];
    }
    if (threadIdx.x < N) Wt[8192 + threadIdx.x] = b[threadIdx.x];
}

// K=KQ*4 -> N=64 layer with lrelu. Warp-private: 8 rows in xbuf (row stride
// xstride floats), outputs to hbuf rows of 64. Lane owns cols 2l,2l+1.
__device__ __forceinline__ void layer_n64(const float* __restrict__ Wt,
                                          const float* __restrict__ xbuf, int xstride,
                                          float* __restrict__ hbuf, int lane, int KQ)
{
    const float2* W = (const float2*)Wt;
    const float2* B = (const float2*)(Wt + 8192);
    float2 b = B[lane];
    float2 a[RPW];
    #pragma unroll
    for (int e = 0; e < RPW; e++) a[e] = b;
    for (int kk = 0; kk < KQ; kk++) {
        float4 x[RPW];
        #pragma unroll
        for (int e = 0; e < RPW; e++) x[e] = ((const float4*)(xbuf + e * xstride))[kk];
        #pragma unroll
        for (int c = 0; c < 4; c++) {
            float2 w = W[(kk * 4 + c) * 32 + lane];
            #pragma unroll
            for (int e = 0; e < RPW; e++) {
                float s = getc(x[e], c);
                a[e].x = fmaf(w.x, s, a[e].x);
                a[e].y = fmaf(w.y, s, a[e].y);
            }
        }
    }
    #pragma unroll
    for (int e = 0; e < RPW; e++) {
        float2 v; v.x = lrelu(a[e].x); v.y = lrelu(a[e].y);
        ((float2*)(hbuf + e * HH))[lane] = v;
    }
}

// K=64 -> N=128 final layer (linear), write to gmem. Lane owns cols 4l..4l+3.
__device__ __forceinline__ void layer_n128_out(const float* __restrict__ Wt,
                                               const float* __restrict__ hbuf,
                                               float* __restrict__ dst0,
                                               float* __restrict__ dst1,
                                               const int* __restrict__ inv,
                                               int mode, int wrow0, int lane)
{
    const float4* W = (const float4*)Wt;
    const float4* B = (const float4*)(Wt + 8192);
    float4 b = B[lane];
    float4 a[RPW];
    #pragma unroll
    for (int e = 0; e < RPW; e++) a[e] = b;
    for (int kk = 0; kk < 16; kk++) {
        float4 x[RPW];
        #pragma unroll
        for (int e = 0; e < RPW; e++) x[e] = ((const float4*)(hbuf + e * HH))[kk];
        #pragma unroll
        for (int c = 0; c < 4; c++) {
            float4 w = W[(kk * 4 + c) * 32 + lane];
            #pragma unroll
            for (int e = 0; e < RPW; e++) {
                float s = getc(x[e], c);
                a[e].x = fmaf(w.x, s, a[e].x);
                a[e].y = fmaf(w.y, s, a[e].y);
                a[e].z = fmaf(w.z, s, a[e].z);
                a[e].w = fmaf(w.w, s, a[e].w);
            }
        }
    }
    #pragma unroll
    for (int e = 0; e < RPW; e++) {
        int grow = wrow0 + e;
        if (grow < N_NODES) {
            bool wr0 = (mode != 2) || (inv[grow] != 0);
            if (wr0) ((float4*)(dst0 + (size_t)grow * H))[lane] = a[e];
            if (mode == 1) ((float4*)(dst1 + (size_t)grow * H))[lane] = a[e];
        }
    }
}

// ---------------------------------------------------------------------------
// Fused 3-layer MLP (128->64->64->128), 64 rows per CTA, staged weights.
// mode 0: X=feat              -> g_invfeat
// mode 1: X=g_neigh/max(deg,1)-> g_invfeat AND out
// mode 2: X=g_invfeat         -> out where inv==1
__global__ void __launch_bounds__(TPB) mlp_kernel(
    int mode, const float* __restrict__ feat, float* __restrict__ out,
    const int* __restrict__ inv,
    const float* __restrict__ w1, const float* __restrict__ b1,
    const float* __restrict__ w2, const float* __restrict__ b2,
    const float* __restrict__ w3, const float* __restrict__ b3)
{
    extern __shared__ __align__(16) float smemf[];
    float* Wt = smemf;
    int tid = threadIdx.x, lane = tid & 31, wid = tid >> 5;
    float* mybuf = smemf + WT_F + wid * 2048;   // X 8x128 | H1 8x64 | H2 8x64
    int wrow0 = blockIdx.x * ROWS_PER_CTA + wid * RPW;

    const float* xsrc = (mode == 0) ? feat : (mode == 1 ? g_neigh : g_invfeat);
    float* dst0 = (mode == 2) ? out : g_invfeat;

    // ---- load this warp's 8 rows (lane = quad index, 32 quads/row) ----
    #pragma unroll
    for (int e = 0; e < RPW; e++) {
        int grow = min(wrow0 + e, N_NODES - 1);
        float4 v = ((const float4*)(xsrc + (size_t)grow * H))[lane];
        if (mode == 1) {
            float s = 1.0f / fmaxf(g_deg[grow], 1.0f);
            v.x *= s; v.y *= s; v.z *= s; v.w *= s;
        }
        ((float4*)(mybuf + e * H))[lane] = v;
    }

    // ---- layer 1: K=128 -> N=64 ----
    stage_w(Wt, w1, b1, 64, 7);
    __syncthreads();
    layer_n64(Wt, mybuf, H, mybuf + 1024, lane, 32);
    __syncthreads();

    // ---- layer 2: K=64 -> N=64 ----
    stage_w(Wt, w2, b2, 64, 6);
    __syncthreads();
    layer_n64(Wt, mybuf + 1024, HH, mybuf + 1536, lane, 16);
    __syncthreads();

    // ---- layer 3: K=64 -> N=128 -> gmem ----
    stage_w(Wt, w3, b3, 128, 6);
    __syncthreads();
    layer_n128_out(Wt, mybuf + 1536, dst0, out, inv, mode, wrow0, lane);
}

// ---------------------------------------------------------------------------
__global__ void zero_kernel()
{
    int idx = blockIdx.x * blockDim.x + threadIdx.x;
    const int total4 = N_NODES * H / 4;
    if (idx < total4) ((float4*)g_neigh)[idx] = make_float4(0.f, 0.f, 0.f, 0.f);
    if (idx < N_NODES) g_deg[idx] = 0.f;
}

// ---------------------------------------------------------------------------
__global__ void edge_kernel(const float* __restrict__ feat,
    const int* __restrict__ src, const int* __restrict__ dst,
    const int* __restrict__ r, int E)
{
    int gw = (blockIdx.x * blockDim.x + threadIdx.x) >> 5;
    int lane = threadIdx.x & 31;
    if (gw >= E) return;
    int s = 0, d = 0, rr = 0;
    if (lane == 0) { s = src[gw]; d = dst[gw]; rr = r[gw]; }
    s = __shfl_sync(0xFFFFFFFFu, s, 0);
    d = __shfl_sync(0xFFFFFFFFu, d, 0);
    rr = __shfl_sync(0xFFFFFFFFu, rr, 0);

    const float* base = rr ? g_invfeat : feat;
    float4 v = ((const float4*)(base + (size_t)s * H))[lane];
    float* p = g_neigh + (size_t)d * H + lane * 4;
    asm volatile("red.global.add.v4.f32 [%0], {%1,%2,%3,%4};"
                 :: "l"(p), "f"(v.x), "f"(v.y), "f"(v.z), "f"(v.w) : "memory");
    if (lane == 0) atomicAdd(&g_deg[d], 1.0f);
}

// ---------------------------------------------------------------------------
extern "C" void kernel_launch(void* const* d_in, const int* in_sizes, int n_in,
                              void* d_out, int out_size)
{
    const float* feat = (const float*)d_in[0];
    const int* src = (const int*)d_in[1];
    const int* dst = (const int*)d_in[2];
    const int* r   = (const int*)d_in[3];
    const int* inv = (const int*)d_in[4];
    const float* iw1 = (const float*)d_in[5],  *ib1 = (const float*)d_in[6];
    const float* iw2 = (const float*)d_in[7],  *ib2 = (const float*)d_in[8];
    const float* iw3 = (const float*)d_in[9],  *ib3 = (const float*)d_in[10];
    const float* aw1 = (const float*)d_in[11], *ab1 = (const float*)d_in[12];
    const float* aw2 = (const float*)d_in[13], *ab2 = (const float*)d_in[14];
    const float* aw3 = (const float*)d_in[15], *ab3 = (const float*)d_in[16];
    int E = in_sizes[1];
    float* out = (float*)d_out;

    cudaFuncSetAttribute(mlp_kernel, cudaFuncAttributeMaxDynamicSharedMemorySize, SMEM_BYTES);

    // 1) zero scratch
    {
        int total4 = N_NODES * H / 4;
        zero_kernel<<<(total4 + 255) / 256, 256>>>();
    }
    // 2) inv_feat = mlp_inv(feat) for all nodes (amortizes edge-side MLP 4x)
    mlp_kernel<<<NT, TPB, SMEM_BYTES>>>(0, feat, out, inv,
                                        iw1, ib1, iw2, ib2, iw3, ib3);
    // 3) edge gather + scatter-add
    edge_kernel<<<(E + 7) / 8, 256>>>(feat, src, dst, r, E);
    // 4) res = mlp_and(neigh/deg) -> g_invfeat AND out
    mlp_kernel<<<NT, TPB, SMEM_BYTES>>>(1, feat, out, inv,
                                        aw1, ab1, aw2, ab2, aw3, ab3);
    // 5) out[inv==1] = mlp_inv(res)
    mlp_kernel<<<NT, TPB, SMEM_BYTES>>>(2, feat, out, inv,
                                        iw1, ib1, iw2, ib2, iw3, ib3);
}

// round 11
// speedup vs baseline: 1.1831x; 1.1020x over previous
#include <cuda_runtime.h>
#include <cstdint>

#define N_NODES 100000
#define H 128
#define HH 64
#define TPB 256
#define WARPS 8
#define RPW 8                               // rows per warp
#define ROWS_PER_CTA (WARPS * RPW)          // 64
#define NT ((N_NODES + ROWS_PER_CTA - 1) / ROWS_PER_CTA)

// ---- scratch (device globals: no allocation allowed) ----
__device__ float g_neigh[(size_t)N_NODES * H];    // 51.2 MB
__device__ float g_invfeat[(size_t)N_NODES * H];  // 51.2 MB (later holds res)
__device__ float g_deg[N_NODES];

// smem (floats): Wt region [8192 weights + 128 bias] | per-warp bufs 1024 each
// (X 8x128 overwritten by H1 8x64 then H2 8x64 in [512,1024))
#define WT_F   8320
#define BUF_F  (WARPS * 1024)
#define SMEM_F (WT_F + BUF_F)
#define SMEM_BYTES (SMEM_F * 4)             // 66048 B -> 3 CTAs/SM if regs allow

__device__ __forceinline__ float lrelu(float x) { return x >= 0.f ? x : 0.01f * x; }
__device__ __forceinline__ float getc(float4 v, int c) {
    return c == 0 ? v.x : c == 1 ? v.y : c == 2 ? v.z : v.w;
}

// ---- packed f32x2 helpers (sm_100 packed fp32 pipe) ----
__device__ __forceinline__ uint64_t pk2(float lo, float hi) {
    uint64_t r;
    asm("mov.b64 %0, {%1, %2};" : "=l"(r) : "f"(lo), "f"(hi));
    return r;
}
__device__ __forceinline__ void upk2(uint64_t v, float& lo, float& hi) {
    asm("mov.b64 {%0, %1}, %2;" : "=f"(lo), "=f"(hi) : "l"(v));
}
__device__ __forceinline__ void fma2(uint64_t& d, uint64_t a, uint64_t b) {
    asm("fma.rn.f32x2 %0, %1, %2, %0;" : "+l"(d) : "l"(a), "l"(b));
}

// stage W [N][2^lgK] row-major -> transposed WtT[k*N + n]; bias -> Wt+8192
__device__ __forceinline__ void stage_w(float* Wt, const float* w, const float* b,
                                        int N, int lgK)
{
    int K = 1 << lgK;
    int tot = N << lgK;
    for (int i = threadIdx.x; i < tot; i += TPB) {
        int n = i >> lgK, k = i & (K - 1);
        Wt[k * N + n] = w[i];
    }
    if (threadIdx.x < N) Wt[8192 + threadIdx.x] = b[threadIdx.x];
}

// K=KQ*4 -> N=64 layer with lrelu, packed over row pairs.
// Lane owns cols (2l, 2l+1). acc pair p covers rows (2p, 2p+1).
__device__ __forceinline__ void layer_n64(const float* __restrict__ Wt,
                                          const float* __restrict__ xbuf, int xstride,
                                          float* __restrict__ hbuf, int lane, int KQ)
{
    const float2* W = (const float2*)Wt;
    const float2* B = (const float2*)(Wt + 8192);
    float2 b = B[lane];
    uint64_t a0[4], a1[4];
    #pragma unroll
    for (int p = 0; p < 4; p++) { a0[p] = pk2(b.x, b.x); a1[p] = pk2(b.y, b.y); }
    for (int kk = 0; kk < KQ; kk++) {
        float4 x[RPW];
        #pragma unroll
        for (int e = 0; e < RPW; e++) x[e] = ((const float4*)(xbuf + e * xstride))[kk];
        #pragma unroll
        for (int c = 0; c < 4; c++) {
            float2 w = W[(kk * 4 + c) * 32 + lane];
            uint64_t w0 = pk2(w.x, w.x), w1 = pk2(w.y, w.y);
            #pragma unroll
            for (int p = 0; p < 4; p++) {
                uint64_t xp = pk2(getc(x[2 * p], c), getc(x[2 * p + 1], c));
                fma2(a0[p], xp, w0);
                fma2(a1[p], xp, w1);
            }
        }
    }
    #pragma unroll
    for (int p = 0; p < 4; p++) {
        float u0, v0, u1, v1;
        upk2(a0[p], u0, v0);  // col y0: rows 2p, 2p+1
        upk2(a1[p], u1, v1);  // col y1
        float2 r0; r0.x = lrelu(u0); r0.y = lrelu(u1);
        float2 r1; r1.x = lrelu(v0); r1.y = lrelu(v1);
        ((float2*)(hbuf + (2 * p) * HH))[lane] = r0;
        ((float2*)(hbuf + (2 * p + 1) * HH))[lane] = r1;
    }
}

// K=64 -> N=128 final layer (linear), packed over row pairs, write to gmem.
// Lane owns cols 4l..4l+3.
__device__ __forceinline__ void layer_n128_out(const float* __restrict__ Wt,
                                               const float* __restrict__ hbuf,
                                               float* __restrict__ dst0,
                                               float* __restrict__ dst1,
                                               const int* __restrict__ inv,
                                               int mode, int wrow0, int lane)
{
    const float4* W = (const float4*)Wt;
    const float4* B = (const float4*)(Wt + 8192);
    float4 b = B[lane];
    uint64_t a0[4], a1[4], a2[4], a3[4];
    #pragma unroll
    for (int p = 0; p < 4; p++) {
        a0[p] = pk2(b.x, b.x); a1[p] = pk2(b.y, b.y);
        a2[p] = pk2(b.z, b.z); a3[p] = pk2(b.w, b.w);
    }
    for (int kk = 0; kk < 16; kk++) {
        float4 x[RPW];
        #pragma unroll
        for (int e = 0; e < RPW; e++) x[e] = ((const float4*)(hbuf + e * HH))[kk];
        #pragma unroll
        for (int c = 0; c < 4; c++) {
            float4 w = W[(kk * 4 + c) * 32 + lane];
            uint64_t w0 = pk2(w.x, w.x), w1 = pk2(w.y, w.y);
            uint64_t w2 = pk2(w.z, w.z), w3 = pk2(w.w, w.w);
            #pragma unroll
            for (int p = 0; p < 4; p++) {
                uint64_t xp = pk2(getc(x[2 * p], c), getc(x[2 * p + 1], c));
                fma2(a0[p], xp, w0);
                fma2(a1[p], xp, w1);
                fma2(a2[p], xp, w2);
                fma2(a3[p], xp, w3);
            }
        }
    }
    #pragma unroll
    for (int p = 0; p < 4; p++) {
        float4 rl, rh;
        { float lo, hi; upk2(a0[p], lo, hi); rl.x = lo; rh.x = hi; }
        { float lo, hi; upk2(a1[p], lo, hi); rl.y = lo; rh.y = hi; }
        { float lo, hi; upk2(a2[p], lo, hi); rl.z = lo; rh.z = hi; }
        { float lo, hi; upk2(a3[p], lo, hi); rl.w = lo; rh.w = hi; }
        int g0 = wrow0 + 2 * p, g1 = g0 + 1;
        if (g0 < N_NODES) {
            if ((mode != 2) || (inv[g0] != 0)) ((float4*)(dst0 + (size_t)g0 * H))[lane] = rl;
            if (mode == 1) ((float4*)(dst1 + (size_t)g0 * H))[lane] = rl;
        }
        if (g1 < N_NODES) {
            if ((mode != 2) || (inv[g1] != 0)) ((float4*)(dst0 + (size_t)g1 * H))[lane] = rh;
            if (mode == 1) ((float4*)(dst1 + (size_t)g1 * H))[lane] = rh;
        }
    }
}

// ---------------------------------------------------------------------------
// Fused 3-layer MLP (128->64->64->128), 64 rows per CTA, staged weights.
// mode 0: X=feat              -> g_invfeat
// mode 1: X=g_neigh/max(deg,1)-> g_invfeat AND out
// mode 2: X=g_invfeat         -> out where inv==1
__global__ void __launch_bounds__(TPB) mlp_kernel(
    int mode, const float* __restrict__ feat, float* __restrict__ out,
    const int* __restrict__ inv,
    const float* __restrict__ w1, const float* __restrict__ b1,
    const float* __restrict__ w2, const float* __restrict__ b2,
    const float* __restrict__ w3, const float* __restrict__ b3)
{
    extern __shared__ __align__(16) float smemf[];
    float* Wt = smemf;
    int tid = threadIdx.x, lane = tid & 31, wid = tid >> 5;
    float* mybuf = smemf + WT_F + wid * 1024;   // X 8x128, then H1 [0,512) H2 [512,1024)
    int wrow0 = blockIdx.x * ROWS_PER_CTA + wid * RPW;

    const float* xsrc = (mode == 0) ? feat : (mode == 1 ? g_neigh : g_invfeat);
    float* dst0 = (mode == 2) ? out : g_invfeat;

    // ---- load this warp's 8 rows (lane = quad index, 32 quads/row) ----
    #pragma unroll
    for (int e = 0; e < RPW; e++) {
        int grow = min(wrow0 + e, N_NODES - 1);
        float4 v = ((const float4*)(xsrc + (size_t)grow * H))[lane];
        if (mode == 1) {
            float s = 1.0f / fmaxf(g_deg[grow], 1.0f);
            v.x *= s; v.y *= s; v.z *= s; v.w *= s;
        }
        ((float4*)(mybuf + e * H))[lane] = v;
    }

    // ---- layer 1: K=128 -> N=64; H1 overwrites X[0,512) (warp-private, reads done) ----
    stage_w(Wt, w1, b1, 64, 7);
    __syncthreads();
    layer_n64(Wt, mybuf, H, mybuf, lane, 32);
    __syncthreads();

    // ---- layer 2: K=64 -> N=64; H2 -> [512,1024) ----
    stage_w(Wt, w2, b2, 64, 6);
    __syncthreads();
    layer_n64(Wt, mybuf, HH, mybuf + 512, lane, 16);
    __syncthreads();

    // ---- layer 3: K=64 -> N=128 -> gmem ----
    stage_w(Wt, w3, b3, 128, 6);
    __syncthreads();
    layer_n128_out(Wt, mybuf + 512, dst0, out, inv, mode, wrow0, lane);
}

// ---------------------------------------------------------------------------
__global__ void zero_kernel()
{
    int idx = blockIdx.x * blockDim.x + threadIdx.x;
    const int total4 = N_NODES * H / 4;
    if (idx < total4) ((float4*)g_neigh)[idx] = make_float4(0.f, 0.f, 0.f, 0.f);
    if (idx < N_NODES) g_deg[idx] = 0.f;
}

// ---------------------------------------------------------------------------
__global__ void edge_kernel(const float* __restrict__ feat,
    const int* __restrict__ src, const int* __restrict__ dst,
    const int* __restrict__ r, int E)
{
    int gw = (blockIdx.x * blockDim.x + threadIdx.x) >> 5;
    int lane = threadIdx.x & 31;
    if (gw >= E) return;
    int s = 0, d = 0, rr = 0;
    if (lane == 0) { s = src[gw]; d = dst[gw]; rr = r[gw]; }
    s = __shfl_sync(0xFFFFFFFFu, s, 0);
    d = __shfl_sync(0xFFFFFFFFu, d, 0);
    rr = __shfl_sync(0xFFFFFFFFu, rr, 0);

    const float* base = rr ? g_invfeat : feat;
    float4 v = ((const float4*)(base + (size_t)s * H))[lane];
    float* p = g_neigh + (size_t)d * H + lane * 4;
    asm volatile("red.global.add.v4.f32 [%0], {%1,%2,%3,%4};"
                 :: "l"(p), "f"(v.x), "f"(v.y), "f"(v.z), "f"(v.w) : "memory");
    if (lane == 0) atomicAdd(&g_deg[d], 1.0f);
}

// ---------------------------------------------------------------------------
extern "C" void kernel_launch(void* const* d_in, const int* in_sizes, int n_in,
                              void* d_out, int out_size)
{
    const float* feat = (const float*)d_in[0];
    const int* src = (const int*)d_in[1];
    const int* dst = (const int*)d_in[2];
    const int* r   = (const int*)d_in[3];
    const int* inv = (const int*)d_in[4];
    const float* iw1 = (const float*)d_in[5],  *ib1 = (const float*)d_in[6];
    const float* iw2 = (const float*)d_in[7],  *ib2 = (const float*)d_in[8];
    const float* iw3 = (const float*)d_in[9],  *ib3 = (const float*)d_in[10];
    const float* aw1 = (const float*)d_in[11], *ab1 = (const float*)d_in[12];
    const float* aw2 = (const float*)d_in[13], *ab2 = (const float*)d_in[14];
    const float* aw3 = (const float*)d_in[15], *ab3 = (const float*)d_in[16];
    int E = in_sizes[1];
    float* out = (float*)d_out;

    cudaFuncSetAttribute(mlp_kernel, cudaFuncAttributeMaxDynamicSharedMemorySize, SMEM_BYTES);

    // 1) zero scratch
    {
        int total4 = N_NODES * H / 4;
        zero_kernel<<<(total4 + 255) / 256, 256>>>();
    }
    // 2) inv_feat = mlp_inv(feat) for all nodes (amortizes edge-side MLP 4x)
    mlp_kernel<<<NT, TPB, SMEM_BYTES>>>(0, feat, out, inv,
                                        iw1, ib1, iw2, ib2, iw3, ib3);
    // 3) edge gather + scatter-add
    edge_kernel<<<(E + 7) / 8, 256>>>(feat, src, dst, r, E);
    // 4) res = mlp_and(neigh/deg) -> g_invfeat AND out
    mlp_kernel<<<NT, TPB, SMEM_BYTES>>>(1, feat, out, inv,
                                        aw1, ab1, aw2, ab2, aw3, ab3);
    // 5) out[inv==1] = mlp_inv(res)
    mlp_kernel<<<NT, TPB, SMEM_BYTES>>>(2, feat, out, inv,
                                        iw1, ib1, iw2, ib2, iw3, ib3);
}